// round 1
// baseline (speedup 1.0000x reference)
#include <cuda_runtime.h>
#include <cuda_bf16.h>

#define BATCH 4
#define SEQ   4096
#define DMODEL 1024
#define HD    64
#define BT    (BATCH * SEQ)

// Scratch for projected Q, K, V (alloc-free rule: __device__ globals)
__device__ float g_Q[BT * HD];
__device__ float g_K[BT * HD];
__device__ float g_V[BT * HD];

// ---------------------------------------------------------------------------
// Projection: out[m][h] = sum_k x[m][k] * w[h][k]
// M = BT (16384), N = HD (64), K = DMODEL (1024)
// grid = (BT/64, 3), block = 256. Each block: 64x64 output tile.
// Thread (tr=tid/16, tc=tid%16) owns a 4x4 micro-tile.
// Tiles stored k-major (transposed) in smem so both operands vectorize.
// ---------------------------------------------------------------------------
__global__ __launch_bounds__(256) void proj_kernel(
    const float* __restrict__ x,
    const float* __restrict__ wq,
    const float* __restrict__ wk,
    const float* __restrict__ wv)
{
    __shared__ float sxT[32][64];   // [k][m]
    __shared__ float swT[32][64];   // [k][h]

    const float* w;
    float* out;
    if (blockIdx.y == 0)      { w = wq; out = g_Q; }
    else if (blockIdx.y == 1) { w = wk; out = g_K; }
    else                      { w = wv; out = g_V; }

    const int tid = threadIdx.x;
    const int tr = tid >> 4;      // 0..15
    const int tc = tid & 15;      // 0..15
    const int row0 = blockIdx.x * 64;

    float acc[4][4] = {};

    for (int k0 = 0; k0 < DMODEL; k0 += 32) {
        // Load x tile (64 rows x 32 k), transposed into smem
        #pragma unroll
        for (int it = 0; it < 2; ++it) {
            int idx = tid + it * 256;          // float4 index, 0..511
            int m  = idx >> 3;                 // 0..63
            int c4 = idx & 7;                  // 0..7
            float4 v = *(const float4*)&x[(size_t)(row0 + m) * DMODEL + k0 + 4 * c4];
            sxT[4 * c4 + 0][m] = v.x;
            sxT[4 * c4 + 1][m] = v.y;
            sxT[4 * c4 + 2][m] = v.z;
            sxT[4 * c4 + 3][m] = v.w;
        }
        // Load w tile (64 h x 32 k), transposed into smem
        #pragma unroll
        for (int it = 0; it < 2; ++it) {
            int idx = tid + it * 256;
            int h  = idx >> 3;
            int c4 = idx & 7;
            float4 v = *(const float4*)&w[(size_t)h * DMODEL + k0 + 4 * c4];
            swT[4 * c4 + 0][h] = v.x;
            swT[4 * c4 + 1][h] = v.y;
            swT[4 * c4 + 2][h] = v.z;
            swT[4 * c4 + 3][h] = v.w;
        }
        __syncthreads();

        #pragma unroll
        for (int kk = 0; kk < 32; ++kk) {
            float4 a = *(const float4*)&sxT[kk][4 * tr];
            float4 b = *(const float4*)&swT[kk][4 * tc];
            float av[4] = {a.x, a.y, a.z, a.w};
            float bv[4] = {b.x, b.y, b.z, b.w};
            #pragma unroll
            for (int i = 0; i < 4; ++i)
                #pragma unroll
                for (int j = 0; j < 4; ++j)
                    acc[i][j] = fmaf(av[i], bv[j], acc[i][j]);
        }
        __syncthreads();
    }

    #pragma unroll
    for (int i = 0; i < 4; ++i) {
        float4 r = make_float4(acc[i][0], acc[i][1], acc[i][2], acc[i][3]);
        *(float4*)&out[(size_t)(row0 + 4 * tr + i) * HD + 4 * tc] = r;
    }
}

// ---------------------------------------------------------------------------
// Flash attention (non-causal), BLOCK_M = 32 query rows, BLOCK_N = 64 keys.
// grid = (SEQ/32, BATCH), block = 256.
// Thread (tr=tid/16, tc=tid%16) owns rows {2tr, 2tr+1}, cols {4tc..4tc+3}.
// Row-group = 16 consecutive lanes -> shfl_xor(1,2,4,8) reductions.
// Smem: sQ 8K + sKT 16K + sV 16K + sP 8K = 49152 B (exactly 48 KB static).
// ---------------------------------------------------------------------------
__global__ __launch_bounds__(256) void attn_kernel(float* __restrict__ out)
{
    __shared__ float sQ[32][64];    // [t][d], pre-scaled by 1/sqrt(HD)
    __shared__ float sKT[64][64];   // [d][s]  (K transposed)
    __shared__ float sV[64][64];    // [s][d]
    __shared__ float sP[32][64];    // probabilities [t][s]

    const int tid = threadIdx.x;
    const int tr = tid >> 4;        // 0..15
    const int tc = tid & 15;        // 0..15
    const int b  = blockIdx.y;
    const int t0 = blockIdx.x * 32;
    const float scale = 0.125f;     // 1/sqrt(64)

    const float* Qg = g_Q + ((size_t)b * SEQ + t0) * HD;

    // Load Q tile (32x64), scaled
    #pragma unroll
    for (int it = 0; it < 2; ++it) {
        int idx = tid + it * 256;   // 0..511 float4
        int r  = idx >> 4;          // 0..31
        int c4 = idx & 15;
        float4 v = *(const float4*)&Qg[(size_t)r * HD + 4 * c4];
        v.x *= scale; v.y *= scale; v.z *= scale; v.w *= scale;
        *(float4*)&sQ[r][4 * c4] = v;
    }

    float m_i[2] = {-1e30f, -1e30f};
    float l_i[2] = {0.f, 0.f};
    float o[2][4] = {};

    for (int s0 = 0; s0 < SEQ; s0 += 64) {
        const float* Kg = g_K + ((size_t)b * SEQ + s0) * HD;
        const float* Vg = g_V + ((size_t)b * SEQ + s0) * HD;

        // K tile transposed into smem
        #pragma unroll
        for (int it = 0; it < 4; ++it) {
            int idx = tid + it * 256;   // 0..1023 float4
            int r  = idx >> 4;          // 0..63
            int c4 = idx & 15;
            float4 v = *(const float4*)&Kg[(size_t)r * HD + 4 * c4];
            sKT[4 * c4 + 0][r] = v.x;
            sKT[4 * c4 + 1][r] = v.y;
            sKT[4 * c4 + 2][r] = v.z;
            sKT[4 * c4 + 3][r] = v.w;
        }
        // V tile row-major
        #pragma unroll
        for (int it = 0; it < 4; ++it) {
            int idx = tid + it * 256;
            int r  = idx >> 4;
            int c4 = idx & 15;
            *(float4*)&sV[r][4 * c4] = *(const float4*)&Vg[(size_t)r * HD + 4 * c4];
        }
        __syncthreads();

        // S = (Q * scale) @ K^T  -> 2x4 per thread
        float s_acc[2][4] = {};
        #pragma unroll
        for (int d = 0; d < 64; ++d) {
            float a0 = sQ[2 * tr + 0][d];
            float a1 = sQ[2 * tr + 1][d];
            float4 bq = *(const float4*)&sKT[d][4 * tc];
            s_acc[0][0] = fmaf(a0, bq.x, s_acc[0][0]);
            s_acc[0][1] = fmaf(a0, bq.y, s_acc[0][1]);
            s_acc[0][2] = fmaf(a0, bq.z, s_acc[0][2]);
            s_acc[0][3] = fmaf(a0, bq.w, s_acc[0][3]);
            s_acc[1][0] = fmaf(a1, bq.x, s_acc[1][0]);
            s_acc[1][1] = fmaf(a1, bq.y, s_acc[1][1]);
            s_acc[1][2] = fmaf(a1, bq.z, s_acc[1][2]);
            s_acc[1][3] = fmaf(a1, bq.w, s_acc[1][3]);
        }

        // Online softmax per row
        #pragma unroll
        for (int i = 0; i < 2; ++i) {
            float mx = fmaxf(fmaxf(s_acc[i][0], s_acc[i][1]),
                             fmaxf(s_acc[i][2], s_acc[i][3]));
            #pragma unroll
            for (int off = 8; off >= 1; off >>= 1)
                mx = fmaxf(mx, __shfl_xor_sync(0xffffffffu, mx, off));
            float m_new = fmaxf(m_i[i], mx);
            float alpha = __expf(m_i[i] - m_new);
            float psum = 0.f;
            #pragma unroll
            for (int j = 0; j < 4; ++j) {
                float p = __expf(s_acc[i][j] - m_new);
                s_acc[i][j] = p;
                psum += p;
            }
            #pragma unroll
            for (int off = 8; off >= 1; off >>= 1)
                psum += __shfl_xor_sync(0xffffffffu, psum, off);
            l_i[i] = l_i[i] * alpha + psum;
            m_i[i] = m_new;
            #pragma unroll
            for (int j = 0; j < 4; ++j) o[i][j] *= alpha;
            *(float4*)&sP[2 * tr + i][4 * tc] =
                make_float4(s_acc[i][0], s_acc[i][1], s_acc[i][2], s_acc[i][3]);
        }
        __syncthreads();

        // O += P @ V
        #pragma unroll
        for (int s = 0; s < 64; ++s) {
            float p0 = sP[2 * tr + 0][s];
            float p1 = sP[2 * tr + 1][s];
            float4 v = *(const float4*)&sV[s][4 * tc];
            o[0][0] = fmaf(p0, v.x, o[0][0]);
            o[0][1] = fmaf(p0, v.y, o[0][1]);
            o[0][2] = fmaf(p0, v.z, o[0][2]);
            o[0][3] = fmaf(p0, v.w, o[0][3]);
            o[1][0] = fmaf(p1, v.x, o[1][0]);
            o[1][1] = fmaf(p1, v.y, o[1][1]);
            o[1][2] = fmaf(p1, v.z, o[1][2]);
            o[1][3] = fmaf(p1, v.w, o[1][3]);
        }
        __syncthreads();   // before next iteration overwrites sKT/sV
    }

    // Normalize and write
    #pragma unroll
    for (int i = 0; i < 2; ++i) {
        float inv = 1.0f / l_i[i];
        float4 r = make_float4(o[i][0] * inv, o[i][1] * inv,
                               o[i][2] * inv, o[i][3] * inv);
        *(float4*)&out[((size_t)b * SEQ + t0 + 2 * tr + i) * HD + 4 * tc] = r;
    }
}

extern "C" void kernel_launch(void* const* d_in, const int* in_sizes, int n_in,
                              void* d_out, int out_size)
{
    const float* x  = (const float*)d_in[0];
    const float* wq = (const float*)d_in[1];
    const float* wk = (const float*)d_in[2];
    const float* wv = (const float*)d_in[3];
    float* out = (float*)d_out;

    dim3 gridP(BT / 64, 3);
    proj_kernel<<<gridP, 256>>>(x, wq, wk, wv);

    dim3 gridA(SEQ / 32, BATCH);
    attn_kernel<<<gridA, 256>>>(out);
}

// round 2
// speedup vs baseline: 2.9024x; 2.9024x over previous
#include <cuda_runtime.h>
#include <cuda_bf16.h>
#include <cstdint>

#define BATCH  4
#define SEQ    4096
#define DMODEL 1024
#define HD     64
#define BT     (BATCH * SEQ)

// Scratch for projected Q, K, V (alloc-free rule: __device__ globals)
__device__ float g_Q[BT * HD];
__device__ float g_K[BT * HD];
__device__ float g_V[BT * HD];

__device__ __forceinline__ uint32_t f2tf32(float f) {
    uint32_t u;
    asm("cvt.rna.tf32.f32 %0, %1;" : "=r"(u) : "f"(f));
    return u;
}

__device__ __forceinline__ void mma_tf32(float c[4],
                                         uint32_t a0, uint32_t a1, uint32_t a2, uint32_t a3,
                                         uint32_t b0, uint32_t b1) {
    asm volatile(
        "mma.sync.aligned.m16n8k8.row.col.f32.tf32.tf32.f32 "
        "{%0,%1,%2,%3}, {%4,%5,%6,%7}, {%8,%9}, {%0,%1,%2,%3};"
        : "+f"(c[0]), "+f"(c[1]), "+f"(c[2]), "+f"(c[3])
        : "r"(a0), "r"(a1), "r"(a2), "r"(a3), "r"(b0), "r"(b1));
}

// ---------------------------------------------------------------------------
// Projection (unchanged from round 1): out[m][h] = sum_k x[m][k] * w[h][k]
// ---------------------------------------------------------------------------
__global__ __launch_bounds__(256) void proj_kernel(
    const float* __restrict__ x,
    const float* __restrict__ wq,
    const float* __restrict__ wk,
    const float* __restrict__ wv)
{
    __shared__ float sxT[32][64];   // [k][m]
    __shared__ float swT[32][64];   // [k][h]

    const float* w;
    float* out;
    if (blockIdx.y == 0)      { w = wq; out = g_Q; }
    else if (blockIdx.y == 1) { w = wk; out = g_K; }
    else                      { w = wv; out = g_V; }

    const int tid = threadIdx.x;
    const int tr = tid >> 4;
    const int tc = tid & 15;
    const int row0 = blockIdx.x * 64;

    float acc[4][4] = {};

    for (int k0 = 0; k0 < DMODEL; k0 += 32) {
        #pragma unroll
        for (int it = 0; it < 2; ++it) {
            int idx = tid + it * 256;
            int m  = idx >> 3;
            int c4 = idx & 7;
            float4 v = *(const float4*)&x[(size_t)(row0 + m) * DMODEL + k0 + 4 * c4];
            sxT[4 * c4 + 0][m] = v.x;
            sxT[4 * c4 + 1][m] = v.y;
            sxT[4 * c4 + 2][m] = v.z;
            sxT[4 * c4 + 3][m] = v.w;
        }
        #pragma unroll
        for (int it = 0; it < 2; ++it) {
            int idx = tid + it * 256;
            int h  = idx >> 3;
            int c4 = idx & 7;
            float4 v = *(const float4*)&w[(size_t)h * DMODEL + k0 + 4 * c4];
            swT[4 * c4 + 0][h] = v.x;
            swT[4 * c4 + 1][h] = v.y;
            swT[4 * c4 + 2][h] = v.z;
            swT[4 * c4 + 3][h] = v.w;
        }
        __syncthreads();

        #pragma unroll
        for (int kk = 0; kk < 32; ++kk) {
            float4 a = *(const float4*)&sxT[kk][4 * tr];
            float4 b = *(const float4*)&swT[kk][4 * tc];
            float av[4] = {a.x, a.y, a.z, a.w};
            float bv[4] = {b.x, b.y, b.z, b.w};
            #pragma unroll
            for (int i = 0; i < 4; ++i)
                #pragma unroll
                for (int j = 0; j < 4; ++j)
                    acc[i][j] = fmaf(av[i], bv[j], acc[i][j]);
        }
        __syncthreads();
    }

    #pragma unroll
    for (int i = 0; i < 4; ++i) {
        float4 r = make_float4(acc[i][0], acc[i][1], acc[i][2], acc[i][3]);
        *(float4*)&out[(size_t)(row0 + 4 * tr + i) * HD + 4 * tc] = r;
    }
}

// ---------------------------------------------------------------------------
// Flash attention: QK^T on tensor cores (tf32 mma.sync), PV in fp32 FMA.
// BLOCK_M = 64 rows, BLOCK_N = 64 keys/iter, 128 threads = 4 warps.
// Warp w owns query rows [16w, 16w+16) x all 64 keys -> softmax is
// intra-warp (shfl over the 4-lane tig group).
// Smem reuse: region A = sQ(tf32) then sV (Q dead after fragment hoist);
//             region B = sK(tf32) then sP^T (K dead after QK mma).
// Strides padded to 68 words -> conflict-free fragment LDS.
// ---------------------------------------------------------------------------
#define BM 64
#define BN 64
#define PADS 68

__global__ __launch_bounds__(128) void attn_kernel(float* __restrict__ out)
{
    __shared__ char smem_raw[BM * PADS * 4 * 2 + 3 * BM * 4];
    uint32_t* sQ  = (uint32_t*)smem_raw;                       // [64][68] tf32
    float*    sV  = (float*)smem_raw;                          // [64][64] (aliases sQ)
    uint32_t* sK  = (uint32_t*)(smem_raw + BM * PADS * 4);     // [64][68] tf32
    float*    sPT = (float*)(smem_raw + BM * PADS * 4);        // [s][m] stride 68 (aliases sK)
    float*    row_m = (float*)(smem_raw + BM * PADS * 4 * 2);
    float*    row_l = row_m + BM;
    float*    sAl   = row_m + 2 * BM;

    const int tid  = threadIdx.x;
    const int warp = tid >> 5;
    const int lane = tid & 31;
    const int gid  = lane >> 2;       // 0..7
    const int tig  = lane & 3;        // 0..3
    const int b    = blockIdx.y;
    const int t0   = blockIdx.x * BM;

    // PV-phase thread tile: rows 4*tr.., cols 8*tc..
    const int tr = tid >> 3;          // 0..15
    const int tc = tid & 7;           // 0..7

    // ---- Load Q (scaled by 1/sqrt(HD), converted to tf32) ----
    const float* Qg = g_Q + ((size_t)b * SEQ + t0) * HD;
    #pragma unroll
    for (int it = 0; it < 8; ++it) {
        int idx = tid + it * 128;
        int r  = idx >> 4;
        int c4 = idx & 15;
        float4 v = *(const float4*)&Qg[(size_t)r * HD + 4 * c4];
        uint4 u;
        u.x = f2tf32(v.x * 0.125f);
        u.y = f2tf32(v.y * 0.125f);
        u.z = f2tf32(v.z * 0.125f);
        u.w = f2tf32(v.w * 0.125f);
        *(uint4*)&sQ[r * PADS + 4 * c4] = u;
    }
    if (tid < BM) { row_m[tid] = -1e30f; row_l[tid] = 0.f; }
    __syncthreads();

    // ---- Hoist Q A-fragments into registers (Q is loop-invariant) ----
    uint32_t Aq[8][4];
    const int mrow = 16 * warp + gid;
    #pragma unroll
    for (int k = 0; k < 8; ++k) {
        Aq[k][0] = sQ[(mrow)     * PADS + 8 * k + tig];
        Aq[k][1] = sQ[(mrow + 8) * PADS + 8 * k + tig];
        Aq[k][2] = sQ[(mrow)     * PADS + 8 * k + tig + 4];
        Aq[k][3] = sQ[(mrow + 8) * PADS + 8 * k + tig + 4];
    }

    float O[4][8] = {};

    for (int s0 = 0; s0 < SEQ; s0 += BN) {
        __syncthreads();   // prev PV done (and Aq hoisted) before overwriting sV/sPT

        // ---- Load K (tf32) and V (fp32) tiles ----
        const float* Kg = g_K + ((size_t)b * SEQ + s0) * HD;
        const float* Vg = g_V + ((size_t)b * SEQ + s0) * HD;
        #pragma unroll
        for (int it = 0; it < 8; ++it) {
            int idx = tid + it * 128;
            int r  = idx >> 4;
            int c4 = idx & 15;
            float4 kv = *(const float4*)&Kg[(size_t)r * HD + 4 * c4];
            uint4 u;
            u.x = f2tf32(kv.x); u.y = f2tf32(kv.y);
            u.z = f2tf32(kv.z); u.w = f2tf32(kv.w);
            *(uint4*)&sK[r * PADS + 4 * c4] = u;
            *(float4*)&sV[r * BN + 4 * c4] = *(const float4*)&Vg[(size_t)r * HD + 4 * c4];
        }
        __syncthreads();

        // ---- S = Q @ K^T on tensor cores ----
        float sacc[8][4] = {};
        #pragma unroll
        for (int k = 0; k < 8; ++k) {
            #pragma unroll
            for (int nc = 0; nc < 8; ++nc) {
                uint32_t b0 = sK[(8 * nc + gid) * PADS + 8 * k + tig];
                uint32_t b1 = sK[(8 * nc + gid) * PADS + 8 * k + tig + 4];
                mma_tf32(sacc[nc], Aq[k][0], Aq[k][1], Aq[k][2], Aq[k][3], b0, b1);
            }
        }

        // ---- Online softmax (rows mrow, mrow+8; intra-warp shfl reduce) ----
        float mx0 = -1e30f, mx1 = -1e30f;
        #pragma unroll
        for (int nc = 0; nc < 8; ++nc) {
            mx0 = fmaxf(mx0, fmaxf(sacc[nc][0], sacc[nc][1]));
            mx1 = fmaxf(mx1, fmaxf(sacc[nc][2], sacc[nc][3]));
        }
        mx0 = fmaxf(mx0, __shfl_xor_sync(0xffffffffu, mx0, 1));
        mx0 = fmaxf(mx0, __shfl_xor_sync(0xffffffffu, mx0, 2));
        mx1 = fmaxf(mx1, __shfl_xor_sync(0xffffffffu, mx1, 1));
        mx1 = fmaxf(mx1, __shfl_xor_sync(0xffffffffu, mx1, 2));

        float mo0 = row_m[mrow], mo1 = row_m[mrow + 8];
        float mn0 = fmaxf(mo0, mx0), mn1 = fmaxf(mo1, mx1);
        float al0 = __expf(mo0 - mn0), al1 = __expf(mo1 - mn1);

        float sum0 = 0.f, sum1 = 0.f;
        #pragma unroll
        for (int nc = 0; nc < 8; ++nc) {
            sacc[nc][0] = __expf(sacc[nc][0] - mn0);
            sacc[nc][1] = __expf(sacc[nc][1] - mn0);
            sacc[nc][2] = __expf(sacc[nc][2] - mn1);
            sacc[nc][3] = __expf(sacc[nc][3] - mn1);
            sum0 += sacc[nc][0] + sacc[nc][1];
            sum1 += sacc[nc][2] + sacc[nc][3];
        }
        sum0 += __shfl_xor_sync(0xffffffffu, sum0, 1);
        sum0 += __shfl_xor_sync(0xffffffffu, sum0, 2);
        sum1 += __shfl_xor_sync(0xffffffffu, sum1, 1);
        sum1 += __shfl_xor_sync(0xffffffffu, sum1, 2);

        if (tig == 0) {
            row_m[mrow]     = mn0;
            row_m[mrow + 8] = mn1;
            row_l[mrow]     = row_l[mrow]     * al0 + sum0;
            row_l[mrow + 8] = row_l[mrow + 8] * al1 + sum1;
            sAl[mrow]     = al0;
            sAl[mrow + 8] = al1;
        }
        __syncthreads();   // all warps done reading sK; sAl/row_l published

        // ---- Write P transposed ([s][m], stride 68) ----
        #pragma unroll
        for (int nc = 0; nc < 8; ++nc) {
            int c0 = 8 * nc + 2 * tig;
            sPT[(c0)     * PADS + mrow]     = sacc[nc][0];
            sPT[(c0 + 1) * PADS + mrow]     = sacc[nc][1];
            sPT[(c0)     * PADS + mrow + 8] = sacc[nc][2];
            sPT[(c0 + 1) * PADS + mrow + 8] = sacc[nc][3];
        }
        __syncthreads();

        // ---- O = O*alpha + P @ V (fp32, fully vectorized) ----
        float al[4];
        #pragma unroll
        for (int i = 0; i < 4; ++i) {
            al[i] = sAl[4 * tr + i];
            #pragma unroll
            for (int j = 0; j < 8; ++j) O[i][j] *= al[i];
        }
        #pragma unroll 8
        for (int s = 0; s < BN; ++s) {
            float4 p  = *(const float4*)&sPT[s * PADS + 4 * tr];
            float4 v0 = *(const float4*)&sV[s * BN + 8 * tc];
            float4 v1 = *(const float4*)&sV[s * BN + 8 * tc + 4];
            float pv[4] = {p.x, p.y, p.z, p.w};
            float vv[8] = {v0.x, v0.y, v0.z, v0.w, v1.x, v1.y, v1.z, v1.w};
            #pragma unroll
            for (int i = 0; i < 4; ++i)
                #pragma unroll
                for (int j = 0; j < 8; ++j)
                    O[i][j] = fmaf(pv[i], vv[j], O[i][j]);
        }
    }

    // ---- Normalize and write ----
    #pragma unroll
    for (int i = 0; i < 4; ++i) {
        float inv = 1.0f / row_l[4 * tr + i];
        float4 r0 = make_float4(O[i][0] * inv, O[i][1] * inv, O[i][2] * inv, O[i][3] * inv);
        float4 r1 = make_float4(O[i][4] * inv, O[i][5] * inv, O[i][6] * inv, O[i][7] * inv);
        float* dst = &out[((size_t)b * SEQ + t0 + 4 * tr + i) * HD + 8 * tc];
        *(float4*)dst = r0;
        *(float4*)(dst + 4) = r1;
    }
}

extern "C" void kernel_launch(void* const* d_in, const int* in_sizes, int n_in,
                              void* d_out, int out_size)
{
    const float* x  = (const float*)d_in[0];
    const float* wq = (const float*)d_in[1];
    const float* wk = (const float*)d_in[2];
    const float* wv = (const float*)d_in[3];
    float* out = (float*)d_out;

    dim3 gridP(BT / 64, 3);
    proj_kernel<<<gridP, 256>>>(x, wq, wk, wv);

    dim3 gridA(SEQ / BM, BATCH);
    attn_kernel<<<gridA, 128>>>(out);
}

// round 3
// speedup vs baseline: 5.5000x; 1.8950x over previous
#include <cuda_runtime.h>
#include <cuda_bf16.h>
#include <cstdint>

#define BATCH  4
#define SEQ    4096
#define DMODEL 1024
#define HD     64
#define BT     (BATCH * SEQ)

// Scratch for projected Q, K, V (alloc-free rule: __device__ globals)
__device__ float g_Q[BT * HD];
__device__ float g_K[BT * HD];
__device__ float g_V[BT * HD];

__device__ __forceinline__ uint32_t f2tf32(float f) {
    uint32_t u;
    asm("cvt.rna.tf32.f32 %0, %1;" : "=r"(u) : "f"(f));
    return u;
}

__device__ __forceinline__ void mma_tf32(float c[4],
                                         uint32_t a0, uint32_t a1, uint32_t a2, uint32_t a3,
                                         uint32_t b0, uint32_t b1) {
    asm volatile(
        "mma.sync.aligned.m16n8k8.row.col.f32.tf32.tf32.f32 "
        "{%0,%1,%2,%3}, {%4,%5,%6,%7}, {%8,%9}, {%0,%1,%2,%3};"
        : "+f"(c[0]), "+f"(c[1]), "+f"(c[2]), "+f"(c[3])
        : "r"(a0), "r"(a1), "r"(a2), "r"(a3), "r"(b0), "r"(b1));
}

// ---------------------------------------------------------------------------
// Fused QKV projection on tensor cores (tf32 mma).
// Each block: 64 rows of x, ALL of Q/K/V (x tile loaded once, not 3x).
// 128 threads = 4 warps; warp w owns rows {16w+gid, 16w+gid+8}.
// Per-warp accumulators: 3 outputs x 8 n-blocks x 4 = 96 regs.
// smem strides padded (36) so every fragment LDS is bank-conflict-free.
// ---------------------------------------------------------------------------
#define PXS 36

__global__ __launch_bounds__(128) void proj_kernel(
    const float* __restrict__ x,
    const float* __restrict__ wq,
    const float* __restrict__ wk,
    const float* __restrict__ wv)
{
    __shared__ uint32_t sX[64 * PXS];        // [m][k] tf32
    __shared__ uint32_t sW[3 * 64 * PXS];    // [o][h][k] tf32

    const int tid  = threadIdx.x;
    const int warp = tid >> 5;
    const int lane = tid & 31;
    const int gid  = lane >> 2;
    const int tig  = lane & 3;
    const int row0 = blockIdx.x * 64;
    const int mrow = 16 * warp + gid;

    const float* ws[3] = {wq, wk, wv};

    float acc[3][8][4] = {};

    for (int k0 = 0; k0 < DMODEL; k0 += 32) {
        __syncthreads();
        // x tile: 64 x 32 -> 512 float4
        #pragma unroll
        for (int it = 0; it < 4; ++it) {
            int idx = tid + it * 128;
            int m  = idx >> 3;
            int c4 = idx & 7;
            float4 v = *(const float4*)&x[(size_t)(row0 + m) * DMODEL + k0 + 4 * c4];
            uint4 u;
            u.x = f2tf32(v.x); u.y = f2tf32(v.y);
            u.z = f2tf32(v.z); u.w = f2tf32(v.w);
            *(uint4*)&sX[m * PXS + 4 * c4] = u;
        }
        // w tiles: 3 x 64 x 32 -> 1536 float4 ; o = it/4 is compile-time
        #pragma unroll
        for (int it = 0; it < 12; ++it) {
            int o   = it >> 2;
            int idx = tid + it * 128 - o * 512;
            int h  = idx >> 3;
            int c4 = idx & 7;
            float4 v = *(const float4*)&ws[o][(size_t)h * DMODEL + k0 + 4 * c4];
            uint4 u;
            u.x = f2tf32(v.x); u.y = f2tf32(v.y);
            u.z = f2tf32(v.z); u.w = f2tf32(v.w);
            *(uint4*)&sW[o * 64 * PXS + h * PXS + 4 * c4] = u;
        }
        __syncthreads();

        #pragma unroll
        for (int ks = 0; ks < 4; ++ks) {
            uint32_t a0 = sX[(mrow)     * PXS + 8 * ks + tig];
            uint32_t a1 = sX[(mrow + 8) * PXS + 8 * ks + tig];
            uint32_t a2 = sX[(mrow)     * PXS + 8 * ks + tig + 4];
            uint32_t a3 = sX[(mrow + 8) * PXS + 8 * ks + tig + 4];
            #pragma unroll
            for (int o = 0; o < 3; ++o) {
                #pragma unroll
                for (int nc = 0; nc < 8; ++nc) {
                    uint32_t b0 = sW[o * 64 * PXS + (8 * nc + gid) * PXS + 8 * ks + tig];
                    uint32_t b1 = sW[o * 64 * PXS + (8 * nc + gid) * PXS + 8 * ks + tig + 4];
                    mma_tf32(acc[o][nc], a0, a1, a2, a3, b0, b1);
                }
            }
        }
    }

    float* outs[3] = {g_Q, g_K, g_V};
    #pragma unroll
    for (int o = 0; o < 3; ++o) {
        #pragma unroll
        for (int nc = 0; nc < 8; ++nc) {
            float* p0 = &outs[o][(size_t)(row0 + mrow) * HD + 8 * nc + 2 * tig];
            float* p1 = &outs[o][(size_t)(row0 + mrow + 8) * HD + 8 * nc + 2 * tig];
            *(float2*)p0 = make_float2(acc[o][nc][0], acc[o][nc][1]);
            *(float2*)p1 = make_float2(acc[o][nc][2], acc[o][nc][3]);
        }
    }
}

// ---------------------------------------------------------------------------
// Flash attention, both GEMMs on tf32 tensor cores.
// BM=64 query rows, BN=64 keys/iter, 128 threads = 4 warps.
// Warp w owns rows {16w+gid, 16w+gid+8}; softmax stats live in registers.
// sKP region: Q tile (hoisted to regs) -> K tile -> P tile (per-warp rows,
// disjoint, so P write->read needs only __syncwarp). sV: tf32, stride 72.
// ---------------------------------------------------------------------------
#define BM 64
#define BN 64
#define SKP 68
#define SVP 72

__global__ __launch_bounds__(128) void attn_kernel(float* __restrict__ out)
{
    __shared__ uint32_t sKP[BM * SKP];   // Q (tf32) -> K (tf32) -> P (tf32)
    __shared__ uint32_t sV [BN * SVP];   // V (tf32)

    const int tid  = threadIdx.x;
    const int warp = tid >> 5;
    const int lane = tid & 31;
    const int gid  = lane >> 2;
    const int tig  = lane & 3;
    const int b    = blockIdx.y;
    const int t0   = blockIdx.x * BM;
    const int mrow = 16 * warp + gid;

    // ---- Load Q (scaled, tf32) into sKP ----
    const float* Qg = g_Q + ((size_t)b * SEQ + t0) * HD;
    #pragma unroll
    for (int it = 0; it < 8; ++it) {
        int idx = tid + it * 128;
        int r  = idx >> 4;
        int c4 = idx & 15;
        float4 v = *(const float4*)&Qg[(size_t)r * HD + 4 * c4];
        uint4 u;
        u.x = f2tf32(v.x * 0.125f);
        u.y = f2tf32(v.y * 0.125f);
        u.z = f2tf32(v.z * 0.125f);
        u.w = f2tf32(v.w * 0.125f);
        *(uint4*)&sKP[r * SKP + 4 * c4] = u;
    }
    __syncthreads();

    // ---- Hoist Q A-fragments (loop-invariant) ----
    uint32_t Aq[8][4];
    #pragma unroll
    for (int k = 0; k < 8; ++k) {
        Aq[k][0] = sKP[(mrow)     * SKP + 8 * k + tig];
        Aq[k][1] = sKP[(mrow + 8) * SKP + 8 * k + tig];
        Aq[k][2] = sKP[(mrow)     * SKP + 8 * k + tig + 4];
        Aq[k][3] = sKP[(mrow + 8) * SKP + 8 * k + tig + 4];
    }

    float O[8][4] = {};
    float m0 = -1e30f, m1 = -1e30f, l0 = 0.f, l1 = 0.f;

    for (int s0 = 0; s0 < SEQ; s0 += BN) {
        __syncthreads();   // prev iter's P/V reads (and Q hoist) complete

        // ---- Load K, V tiles (tf32) ----
        const float* Kg = g_K + ((size_t)b * SEQ + s0) * HD;
        const float* Vg = g_V + ((size_t)b * SEQ + s0) * HD;
        #pragma unroll
        for (int it = 0; it < 8; ++it) {
            int idx = tid + it * 128;
            int r  = idx >> 4;
            int c4 = idx & 15;
            float4 kv = *(const float4*)&Kg[(size_t)r * HD + 4 * c4];
            uint4 uk;
            uk.x = f2tf32(kv.x); uk.y = f2tf32(kv.y);
            uk.z = f2tf32(kv.z); uk.w = f2tf32(kv.w);
            *(uint4*)&sKP[r * SKP + 4 * c4] = uk;
            float4 vv = *(const float4*)&Vg[(size_t)r * HD + 4 * c4];
            uint4 uv;
            uv.x = f2tf32(vv.x); uv.y = f2tf32(vv.y);
            uv.z = f2tf32(vv.z); uv.w = f2tf32(vv.w);
            *(uint4*)&sV[r * SVP + 4 * c4] = uv;
        }
        __syncthreads();

        // ---- S = Q @ K^T (tensor) ----
        float sacc[8][4] = {};
        #pragma unroll
        for (int k = 0; k < 8; ++k) {
            #pragma unroll
            for (int nc = 0; nc < 8; ++nc) {
                uint32_t b0 = sKP[(8 * nc + gid) * SKP + 8 * k + tig];
                uint32_t b1 = sKP[(8 * nc + gid) * SKP + 8 * k + tig + 4];
                mma_tf32(sacc[nc], Aq[k][0], Aq[k][1], Aq[k][2], Aq[k][3], b0, b1);
            }
        }

        // ---- Online softmax in registers ----
        float mx0 = -1e30f, mx1 = -1e30f;
        #pragma unroll
        for (int nc = 0; nc < 8; ++nc) {
            mx0 = fmaxf(mx0, fmaxf(sacc[nc][0], sacc[nc][1]));
            mx1 = fmaxf(mx1, fmaxf(sacc[nc][2], sacc[nc][3]));
        }
        mx0 = fmaxf(mx0, __shfl_xor_sync(0xffffffffu, mx0, 1));
        mx0 = fmaxf(mx0, __shfl_xor_sync(0xffffffffu, mx0, 2));
        mx1 = fmaxf(mx1, __shfl_xor_sync(0xffffffffu, mx1, 1));
        mx1 = fmaxf(mx1, __shfl_xor_sync(0xffffffffu, mx1, 2));

        float mn0 = fmaxf(m0, mx0), mn1 = fmaxf(m1, mx1);
        float al0 = __expf(m0 - mn0), al1 = __expf(m1 - mn1);

        float sum0 = 0.f, sum1 = 0.f;
        #pragma unroll
        for (int nc = 0; nc < 8; ++nc) {
            sacc[nc][0] = __expf(sacc[nc][0] - mn0);
            sacc[nc][1] = __expf(sacc[nc][1] - mn0);
            sacc[nc][2] = __expf(sacc[nc][2] - mn1);
            sacc[nc][3] = __expf(sacc[nc][3] - mn1);
            sum0 += sacc[nc][0] + sacc[nc][1];
            sum1 += sacc[nc][2] + sacc[nc][3];
        }
        sum0 += __shfl_xor_sync(0xffffffffu, sum0, 1);
        sum0 += __shfl_xor_sync(0xffffffffu, sum0, 2);
        sum1 += __shfl_xor_sync(0xffffffffu, sum1, 1);
        sum1 += __shfl_xor_sync(0xffffffffu, sum1, 2);

        l0 = l0 * al0 + sum0;  m0 = mn0;
        l1 = l1 * al1 + sum1;  m1 = mn1;

        #pragma unroll
        for (int nc = 0; nc < 8; ++nc) {
            O[nc][0] *= al0; O[nc][1] *= al0;
            O[nc][2] *= al1; O[nc][3] *= al1;
        }

        __syncthreads();   // all warps finished reading sK before P overwrite

        // ---- Write P (tf32) to own rows of sKP ----
        #pragma unroll
        for (int nc = 0; nc < 8; ++nc) {
            int c = 8 * nc + 2 * tig;
            *(uint2*)&sKP[(mrow)     * SKP + c] =
                make_uint2(f2tf32(sacc[nc][0]), f2tf32(sacc[nc][1]));
            *(uint2*)&sKP[(mrow + 8) * SKP + c] =
                make_uint2(f2tf32(sacc[nc][2]), f2tf32(sacc[nc][3]));
        }
        __syncwarp();      // warp-private rows: warp-level ordering suffices

        // ---- O += P @ V (tensor) ----
        #pragma unroll
        for (int ks = 0; ks < 8; ++ks) {
            uint32_t a0 = sKP[(mrow)     * SKP + 8 * ks + tig];
            uint32_t a1 = sKP[(mrow + 8) * SKP + 8 * ks + tig];
            uint32_t a2 = sKP[(mrow)     * SKP + 8 * ks + tig + 4];
            uint32_t a3 = sKP[(mrow + 8) * SKP + 8 * ks + tig + 4];
            #pragma unroll
            for (int nc = 0; nc < 8; ++nc) {
                uint32_t b0 = sV[(8 * ks + tig)     * SVP + 8 * nc + gid];
                uint32_t b1 = sV[(8 * ks + tig + 4) * SVP + 8 * nc + gid];
                mma_tf32(O[nc], a0, a1, a2, a3, b0, b1);
            }
        }
    }

    // ---- Normalize and write (accumulator layout: rows mrow/mrow+8) ----
    float inv0 = 1.0f / l0, inv1 = 1.0f / l1;
    #pragma unroll
    for (int nc = 0; nc < 8; ++nc) {
        int c = 8 * nc + 2 * tig;
        float* p0 = &out[((size_t)b * SEQ + t0 + mrow)     * HD + c];
        float* p1 = &out[((size_t)b * SEQ + t0 + mrow + 8) * HD + c];
        *(float2*)p0 = make_float2(O[nc][0] * inv0, O[nc][1] * inv0);
        *(float2*)p1 = make_float2(O[nc][2] * inv1, O[nc][3] * inv1);
    }
}

extern "C" void kernel_launch(void* const* d_in, const int* in_sizes, int n_in,
                              void* d_out, int out_size)
{
    const float* x  = (const float*)d_in[0];
    const float* wq = (const float*)d_in[1];
    const float* wk = (const float*)d_in[2];
    const float* wv = (const float*)d_in[3];
    float* out = (float*)d_out;

    proj_kernel<<<BT / 64, 128>>>(x, wq, wk, wv);

    dim3 gridA(SEQ / BM, BATCH);
    attn_kernel<<<gridA, 128>>>(out);
}

// round 4
// speedup vs baseline: 8.1808x; 1.4874x over previous
#include <cuda_runtime.h>
#include <cuda_bf16.h>
#include <cstdint>

#define BATCH  4
#define SEQ    4096
#define DMODEL 1024
#define HD     64
#define BT     (BATCH * SEQ)

// Scratch for projected Q, K, V (alloc-free rule: __device__ globals)
__device__ float g_Q[BT * HD];
__device__ float g_K[BT * HD];
__device__ float g_V[BT * HD];

__device__ __forceinline__ uint32_t f2tf32(float f) {
    uint32_t u;
    asm("cvt.rna.tf32.f32 %0, %1;" : "=r"(u) : "f"(f));
    return u;
}

__device__ __forceinline__ void mma_tf32(float c[4],
                                         uint32_t a0, uint32_t a1, uint32_t a2, uint32_t a3,
                                         uint32_t b0, uint32_t b1) {
    asm volatile(
        "mma.sync.aligned.m16n8k8.row.col.f32.tf32.tf32.f32 "
        "{%0,%1,%2,%3}, {%4,%5,%6,%7}, {%8,%9}, {%0,%1,%2,%3};"
        : "+f"(c[0]), "+f"(c[1]), "+f"(c[2]), "+f"(c[3])
        : "r"(a0), "r"(a1), "r"(a2), "r"(a3), "r"(b0), "r"(b1));
}

// ---------------------------------------------------------------------------
// Fused QKV projection on tensor cores (tf32 mma).
// Each block: 64 rows of x, ALL of Q/K/V (x tile loaded once, not 3x).
// 128 threads = 4 warps; warp w owns rows {16w+gid, 16w+gid+8}.
// Per-warp accumulators: 3 outputs x 8 n-blocks x 4 = 96 regs.
// smem strides padded (36) so every fragment LDS is bank-conflict-free.
// ---------------------------------------------------------------------------
#define PXS 36

__global__ __launch_bounds__(128) void proj_kernel(
    const float* __restrict__ x,
    const float* __restrict__ wq,
    const float* __restrict__ wk,
    const float* __restrict__ wv)
{
    __shared__ uint32_t sX[64 * PXS];        // [m][k] tf32
    __shared__ uint32_t sW[3 * 64 * PXS];    // [o][h][k] tf32

    const int tid  = threadIdx.x;
    const int warp = tid >> 5;
    const int lane = tid & 31;
    const int gid  = lane >> 2;
    const int tig  = lane & 3;
    const int row0 = blockIdx.x * 64;
    const int mrow = 16 * warp + gid;

    const float* ws[3] = {wq, wk, wv};

    float acc[3][8][4] = {};

    for (int k0 = 0; k0 < DMODEL; k0 += 32) {
        __syncthreads();
        // x tile: 64 x 32 -> 512 float4
        #pragma unroll
        for (int it = 0; it < 4; ++it) {
            int idx = tid + it * 128;
            int m  = idx >> 3;
            int c4 = idx & 7;
            float4 v = *(const float4*)&x[(size_t)(row0 + m) * DMODEL + k0 + 4 * c4];
            uint4 u;
            u.x = f2tf32(v.x); u.y = f2tf32(v.y);
            u.z = f2tf32(v.z); u.w = f2tf32(v.w);
            *(uint4*)&sX[m * PXS + 4 * c4] = u;
        }
        // w tiles: 3 x 64 x 32 -> 1536 float4 ; o = it/4 is compile-time
        #pragma unroll
        for (int it = 0; it < 12; ++it) {
            int o   = it >> 2;
            int idx = tid + it * 128 - o * 512;
            int h  = idx >> 3;
            int c4 = idx & 7;
            float4 v = *(const float4*)&ws[o][(size_t)h * DMODEL + k0 + 4 * c4];
            uint4 u;
            u.x = f2tf32(v.x); u.y = f2tf32(v.y);
            u.z = f2tf32(v.z); u.w = f2tf32(v.w);
            *(uint4*)&sW[o * 64 * PXS + h * PXS + 4 * c4] = u;
        }
        __syncthreads();

        #pragma unroll
        for (int ks = 0; ks < 4; ++ks) {
            uint32_t a0 = sX[(mrow)     * PXS + 8 * ks + tig];
            uint32_t a1 = sX[(mrow + 8) * PXS + 8 * ks + tig];
            uint32_t a2 = sX[(mrow)     * PXS + 8 * ks + tig + 4];
            uint32_t a3 = sX[(mrow + 8) * PXS + 8 * ks + tig + 4];
            #pragma unroll
            for (int o = 0; o < 3; ++o) {
                #pragma unroll
                for (int nc = 0; nc < 8; ++nc) {
                    uint32_t b0 = sW[o * 64 * PXS + (8 * nc + gid) * PXS + 8 * ks + tig];
                    uint32_t b1 = sW[o * 64 * PXS + (8 * nc + gid) * PXS + 8 * ks + tig + 4];
                    mma_tf32(acc[o][nc], a0, a1, a2, a3, b0, b1);
                }
            }
        }
    }

    float* outs[3] = {g_Q, g_K, g_V};
    #pragma unroll
    for (int o = 0; o < 3; ++o) {
        #pragma unroll
        for (int nc = 0; nc < 8; ++nc) {
            float* p0 = &outs[o][(size_t)(row0 + mrow) * HD + 8 * nc + 2 * tig];
            float* p1 = &outs[o][(size_t)(row0 + mrow + 8) * HD + 8 * nc + 2 * tig];
            *(float2*)p0 = make_float2(acc[o][nc][0], acc[o][nc][1]);
            *(float2*)p1 = make_float2(acc[o][nc][2], acc[o][nc][3]);
        }
    }
}

// ---------------------------------------------------------------------------
// Flash attention, both GEMMs on tf32 tensor cores.
// BM=64 query rows, BN=64 keys/iter, 128 threads = 4 warps.
// Warp w owns rows {16w+gid, 16w+gid+8}; softmax stats live in registers.
// sKP region: Q tile (hoisted to regs) -> K tile -> P tile (per-warp rows,
// disjoint, so P write->read needs only __syncwarp). sV: tf32, stride 72.
// ---------------------------------------------------------------------------
#define BM 64
#define BN 64
#define SKP 68
#define SVP 72

__global__ __launch_bounds__(128) void attn_kernel(float* __restrict__ out)
{
    __shared__ uint32_t sKP[BM * SKP];   // Q (tf32) -> K (tf32) -> P (tf32)
    __shared__ uint32_t sV [BN * SVP];   // V (tf32)

    const int tid  = threadIdx.x;
    const int warp = tid >> 5;
    const int lane = tid & 31;
    const int gid  = lane >> 2;
    const int tig  = lane & 3;
    const int b    = blockIdx.y;
    const int t0   = blockIdx.x * BM;
    const int mrow = 16 * warp + gid;

    // ---- Load Q (scaled, tf32) into sKP ----
    const float* Qg = g_Q + ((size_t)b * SEQ + t0) * HD;
    #pragma unroll
    for (int it = 0; it < 8; ++it) {
        int idx = tid + it * 128;
        int r  = idx >> 4;
        int c4 = idx & 15;
        float4 v = *(const float4*)&Qg[(size_t)r * HD + 4 * c4];
        uint4 u;
        u.x = f2tf32(v.x * 0.125f);
        u.y = f2tf32(v.y * 0.125f);
        u.z = f2tf32(v.z * 0.125f);
        u.w = f2tf32(v.w * 0.125f);
        *(uint4*)&sKP[r * SKP + 4 * c4] = u;
    }
    __syncthreads();

    // ---- Hoist Q A-fragments (loop-invariant) ----
    uint32_t Aq[8][4];
    #pragma unroll
    for (int k = 0; k < 8; ++k) {
        Aq[k][0] = sKP[(mrow)     * SKP + 8 * k + tig];
        Aq[k][1] = sKP[(mrow + 8) * SKP + 8 * k + tig];
        Aq[k][2] = sKP[(mrow)     * SKP + 8 * k + tig + 4];
        Aq[k][3] = sKP[(mrow + 8) * SKP + 8 * k + tig + 4];
    }

    float O[8][4] = {};
    float m0 = -1e30f, m1 = -1e30f, l0 = 0.f, l1 = 0.f;

    for (int s0 = 0; s0 < SEQ; s0 += BN) {
        __syncthreads();   // prev iter's P/V reads (and Q hoist) complete

        // ---- Load K, V tiles (tf32) ----
        const float* Kg = g_K + ((size_t)b * SEQ + s0) * HD;
        const float* Vg = g_V + ((size_t)b * SEQ + s0) * HD;
        #pragma unroll
        for (int it = 0; it < 8; ++it) {
            int idx = tid + it * 128;
            int r  = idx >> 4;
            int c4 = idx & 15;
            float4 kv = *(const float4*)&Kg[(size_t)r * HD + 4 * c4];
            uint4 uk;
            uk.x = f2tf32(kv.x); uk.y = f2tf32(kv.y);
            uk.z = f2tf32(kv.z); uk.w = f2tf32(kv.w);
            *(uint4*)&sKP[r * SKP + 4 * c4] = uk;
            float4 vv = *(const float4*)&Vg[(size_t)r * HD + 4 * c4];
            uint4 uv;
            uv.x = f2tf32(vv.x); uv.y = f2tf32(vv.y);
            uv.z = f2tf32(vv.z); uv.w = f2tf32(vv.w);
            *(uint4*)&sV[r * SVP + 4 * c4] = uv;
        }
        __syncthreads();

        // ---- S = Q @ K^T (tensor) ----
        float sacc[8][4] = {};
        #pragma unroll
        for (int k = 0; k < 8; ++k) {
            #pragma unroll
            for (int nc = 0; nc < 8; ++nc) {
                uint32_t b0 = sKP[(8 * nc + gid) * SKP + 8 * k + tig];
                uint32_t b1 = sKP[(8 * nc + gid) * SKP + 8 * k + tig + 4];
                mma_tf32(sacc[nc], Aq[k][0], Aq[k][1], Aq[k][2], Aq[k][3], b0, b1);
            }
        }

        // ---- Online softmax in registers ----
        float mx0 = -1e30f, mx1 = -1e30f;
        #pragma unroll
        for (int nc = 0; nc < 8; ++nc) {
            mx0 = fmaxf(mx0, fmaxf(sacc[nc][0], sacc[nc][1]));
            mx1 = fmaxf(mx1, fmaxf(sacc[nc][2], sacc[nc][3]));
        }
        mx0 = fmaxf(mx0, __shfl_xor_sync(0xffffffffu, mx0, 1));
        mx0 = fmaxf(mx0, __shfl_xor_sync(0xffffffffu, mx0, 2));
        mx1 = fmaxf(mx1, __shfl_xor_sync(0xffffffffu, mx1, 1));
        mx1 = fmaxf(mx1, __shfl_xor_sync(0xffffffffu, mx1, 2));

        float mn0 = fmaxf(m0, mx0), mn1 = fmaxf(m1, mx1);
        float al0 = __expf(m0 - mn0), al1 = __expf(m1 - mn1);

        float sum0 = 0.f, sum1 = 0.f;
        #pragma unroll
        for (int nc = 0; nc < 8; ++nc) {
            sacc[nc][0] = __expf(sacc[nc][0] - mn0);
            sacc[nc][1] = __expf(sacc[nc][1] - mn0);
            sacc[nc][2] = __expf(sacc[nc][2] - mn1);
            sacc[nc][3] = __expf(sacc[nc][3] - mn1);
            sum0 += sacc[nc][0] + sacc[nc][1];
            sum1 += sacc[nc][2] + sacc[nc][3];
        }
        sum0 += __shfl_xor_sync(0xffffffffu, sum0, 1);
        sum0 += __shfl_xor_sync(0xffffffffu, sum0, 2);
        sum1 += __shfl_xor_sync(0xffffffffu, sum1, 1);
        sum1 += __shfl_xor_sync(0xffffffffu, sum1, 2);

        l0 = l0 * al0 + sum0;  m0 = mn0;
        l1 = l1 * al1 + sum1;  m1 = mn1;

        #pragma unroll
        for (int nc = 0; nc < 8; ++nc) {
            O[nc][0] *= al0; O[nc][1] *= al0;
            O[nc][2] *= al1; O[nc][3] *= al1;
        }

        __syncthreads();   // all warps finished reading sK before P overwrite

        // ---- Write P (tf32) to own rows of sKP ----
        #pragma unroll
        for (int nc = 0; nc < 8; ++nc) {
            int c = 8 * nc + 2 * tig;
            *(uint2*)&sKP[(mrow)     * SKP + c] =
                make_uint2(f2tf32(sacc[nc][0]), f2tf32(sacc[nc][1]));
            *(uint2*)&sKP[(mrow + 8) * SKP + c] =
                make_uint2(f2tf32(sacc[nc][2]), f2tf32(sacc[nc][3]));
        }
        __syncwarp();      // warp-private rows: warp-level ordering suffices

        // ---- O += P @ V (tensor) ----
        #pragma unroll
        for (int ks = 0; ks < 8; ++ks) {
            uint32_t a0 = sKP[(mrow)     * SKP + 8 * ks + tig];
            uint32_t a1 = sKP[(mrow + 8) * SKP + 8 * ks + tig];
            uint32_t a2 = sKP[(mrow)     * SKP + 8 * ks + tig + 4];
            uint32_t a3 = sKP[(mrow + 8) * SKP + 8 * ks + tig + 4];
            #pragma unroll
            for (int nc = 0; nc < 8; ++nc) {
                uint32_t b0 = sV[(8 * ks + tig)     * SVP + 8 * nc + gid];
                uint32_t b1 = sV[(8 * ks + tig + 4) * SVP + 8 * nc + gid];
                mma_tf32(O[nc], a0, a1, a2, a3, b0, b1);
            }
        }
    }

    // ---- Normalize and write (accumulator layout: rows mrow/mrow+8) ----
    float inv0 = 1.0f / l0, inv1 = 1.0f / l1;
    #pragma unroll
    for (int nc = 0; nc < 8; ++nc) {
        int c = 8 * nc + 2 * tig;
        float* p0 = &out[((size_t)b * SEQ + t0 + mrow)     * HD + c];
        float* p1 = &out[((size_t)b * SEQ + t0 + mrow + 8) * HD + c];
        *(float2*)p0 = make_float2(O[nc][0] * inv0, O[nc][1] * inv0);
        *(float2*)p1 = make_float2(O[nc][2] * inv1, O[nc][3] * inv1);
    }
}

extern "C" void kernel_launch(void* const* d_in, const int* in_sizes, int n_in,
                              void* d_out, int out_size)
{
    const float* x  = (const float*)d_in[0];
    const float* wq = (const float*)d_in[1];
    const float* wk = (const float*)d_in[2];
    const float* wv = (const float*)d_in[3];
    float* out = (float*)d_out;

    proj_kernel<<<BT / 64, 128>>>(x, wq, wk, wv);

    dim3 gridA(SEQ / BM, BATCH);
    attn_kernel<<<gridA, 128>>>(out);
}

// round 5
// speedup vs baseline: 9.3428x; 1.1420x over previous
#include <cuda_runtime.h>
#include <cuda_bf16.h>
#include <cstdint>

#define BATCH  4
#define SEQ    4096
#define DMODEL 1024
#define HD     64
#define BT     (BATCH * SEQ)
#define NSPLIT 4
#define SPLEN  (SEQ / NSPLIT)

// Scratch (alloc-free rule: __device__ globals)
__device__ float g_Q[BT * HD];
__device__ float g_K[BT * HD];
__device__ float g_V[BT * HD];
__device__ float g_O4[NSPLIT * BT * HD];   // unnormalized partial O
__device__ float g_M4[NSPLIT * BT];        // running max per row
__device__ float g_L4[NSPLIT * BT];        // running denom per row

__device__ __forceinline__ uint32_t f2tf32(float f) {
    uint32_t u;
    asm("cvt.rna.tf32.f32 %0, %1;" : "=r"(u) : "f"(f));
    return u;
}

__device__ __forceinline__ void mma_tf32(float c[4],
                                         uint32_t a0, uint32_t a1, uint32_t a2, uint32_t a3,
                                         uint32_t b0, uint32_t b1) {
    asm volatile(
        "mma.sync.aligned.m16n8k8.row.col.f32.tf32.tf32.f32 "
        "{%0,%1,%2,%3}, {%4,%5,%6,%7}, {%8,%9}, {%0,%1,%2,%3};"
        : "+f"(c[0]), "+f"(c[1]), "+f"(c[2]), "+f"(c[3])
        : "r"(a0), "r"(a1), "r"(a2), "r"(a3), "r"(b0), "r"(b1));
}

// ---------------------------------------------------------------------------
// Fused QKV projection on tensor cores (tf32 mma). Unchanged from round 4.
// ---------------------------------------------------------------------------
#define PXS 36

__global__ __launch_bounds__(128) void proj_kernel(
    const float* __restrict__ x,
    const float* __restrict__ wq,
    const float* __restrict__ wk,
    const float* __restrict__ wv)
{
    __shared__ uint32_t sX[64 * PXS];
    __shared__ uint32_t sW[3 * 64 * PXS];

    const int tid  = threadIdx.x;
    const int warp = tid >> 5;
    const int lane = tid & 31;
    const int gid  = lane >> 2;
    const int tig  = lane & 3;
    const int row0 = blockIdx.x * 64;
    const int mrow = 16 * warp + gid;

    const float* ws[3] = {wq, wk, wv};

    float acc[3][8][4] = {};

    for (int k0 = 0; k0 < DMODEL; k0 += 32) {
        __syncthreads();
        #pragma unroll
        for (int it = 0; it < 4; ++it) {
            int idx = tid + it * 128;
            int m  = idx >> 3;
            int c4 = idx & 7;
            float4 v = *(const float4*)&x[(size_t)(row0 + m) * DMODEL + k0 + 4 * c4];
            uint4 u;
            u.x = f2tf32(v.x); u.y = f2tf32(v.y);
            u.z = f2tf32(v.z); u.w = f2tf32(v.w);
            *(uint4*)&sX[m * PXS + 4 * c4] = u;
        }
        #pragma unroll
        for (int it = 0; it < 12; ++it) {
            int o   = it >> 2;
            int idx = tid + it * 128 - o * 512;
            int h  = idx >> 3;
            int c4 = idx & 7;
            float4 v = *(const float4*)&ws[o][(size_t)h * DMODEL + k0 + 4 * c4];
            uint4 u;
            u.x = f2tf32(v.x); u.y = f2tf32(v.y);
            u.z = f2tf32(v.z); u.w = f2tf32(v.w);
            *(uint4*)&sW[o * 64 * PXS + h * PXS + 4 * c4] = u;
        }
        __syncthreads();

        #pragma unroll
        for (int ks = 0; ks < 4; ++ks) {
            uint32_t a0 = sX[(mrow)     * PXS + 8 * ks + tig];
            uint32_t a1 = sX[(mrow + 8) * PXS + 8 * ks + tig];
            uint32_t a2 = sX[(mrow)     * PXS + 8 * ks + tig + 4];
            uint32_t a3 = sX[(mrow + 8) * PXS + 8 * ks + tig + 4];
            #pragma unroll
            for (int o = 0; o < 3; ++o) {
                #pragma unroll
                for (int nc = 0; nc < 8; ++nc) {
                    uint32_t b0 = sW[o * 64 * PXS + (8 * nc + gid) * PXS + 8 * ks + tig];
                    uint32_t b1 = sW[o * 64 * PXS + (8 * nc + gid) * PXS + 8 * ks + tig + 4];
                    mma_tf32(acc[o][nc], a0, a1, a2, a3, b0, b1);
                }
            }
        }
    }

    float* outs[3] = {g_Q, g_K, g_V};
    #pragma unroll
    for (int o = 0; o < 3; ++o) {
        #pragma unroll
        for (int nc = 0; nc < 8; ++nc) {
            float* p0 = &outs[o][(size_t)(row0 + mrow) * HD + 8 * nc + 2 * tig];
            float* p1 = &outs[o][(size_t)(row0 + mrow + 8) * HD + 8 * nc + 2 * tig];
            *(float2*)p0 = make_float2(acc[o][nc][0], acc[o][nc][1]);
            *(float2*)p1 = make_float2(acc[o][nc][2], acc[o][nc][3]);
        }
    }
}

// ---------------------------------------------------------------------------
// Flash attention, split-KV. grid = (SEQ/BM, BATCH, NSPLIT).
// Both GEMMs tf32 mma. P never touches smem: the S-accumulator ->
// A-fragment layout conversion is done with intra-quad shuffles.
// Writes unnormalized O + (m,l) to scratch; combine_kernel merges splits.
// ---------------------------------------------------------------------------
#define BM 64
#define BN 64
#define SKP 68
#define SVP 72

__global__ __launch_bounds__(128, 4) void attn_kernel()
{
    __shared__ uint32_t sQK[BM * SKP];   // Q (tf32) then K (tf32)
    __shared__ uint32_t sV [BN * SVP];   // V (tf32)

    const int tid  = threadIdx.x;
    const int warp = tid >> 5;
    const int lane = tid & 31;
    const int gid  = lane >> 2;
    const int tig  = lane & 3;
    const int b    = blockIdx.y;
    const int t0   = blockIdx.x * BM;
    const int split = blockIdx.z;
    const int mrow = 16 * warp + gid;

    // ---- Load Q (scaled, tf32) ----
    const float* Qg = g_Q + ((size_t)b * SEQ + t0) * HD;
    #pragma unroll
    for (int it = 0; it < 8; ++it) {
        int idx = tid + it * 128;
        int r  = idx >> 4;
        int c4 = idx & 15;
        float4 v = *(const float4*)&Qg[(size_t)r * HD + 4 * c4];
        uint4 u;
        u.x = f2tf32(v.x * 0.125f);
        u.y = f2tf32(v.y * 0.125f);
        u.z = f2tf32(v.z * 0.125f);
        u.w = f2tf32(v.w * 0.125f);
        *(uint4*)&sQK[r * SKP + 4 * c4] = u;
    }
    __syncthreads();

    // ---- Hoist Q A-fragments ----
    uint32_t Aq[8][4];
    #pragma unroll
    for (int k = 0; k < 8; ++k) {
        Aq[k][0] = sQK[(mrow)     * SKP + 8 * k + tig];
        Aq[k][1] = sQK[(mrow + 8) * SKP + 8 * k + tig];
        Aq[k][2] = sQK[(mrow)     * SKP + 8 * k + tig + 4];
        Aq[k][3] = sQK[(mrow + 8) * SKP + 8 * k + tig + 4];
    }

    float O[8][4] = {};
    float m0 = -1e30f, m1 = -1e30f, l0 = 0.f, l1 = 0.f;

    const int sbeg = split * SPLEN;
    const int send = sbeg + SPLEN;

    // shuffle source lanes for P fragment conversion (within 4-lane quad)
    const int src0 = (lane & 28) | (tig >> 1);
    const int src2 = src0 | 2;
    const bool odd = (tig & 1);

    for (int s0 = sbeg; s0 < send; s0 += BN) {
        __syncthreads();   // prev iter's K/V reads (and Q hoist) complete

        const float* Kg = g_K + ((size_t)b * SEQ + s0) * HD;
        const float* Vg = g_V + ((size_t)b * SEQ + s0) * HD;
        #pragma unroll
        for (int it = 0; it < 8; ++it) {
            int idx = tid + it * 128;
            int r  = idx >> 4;
            int c4 = idx & 15;
            float4 kv = *(const float4*)&Kg[(size_t)r * HD + 4 * c4];
            uint4 uk;
            uk.x = f2tf32(kv.x); uk.y = f2tf32(kv.y);
            uk.z = f2tf32(kv.z); uk.w = f2tf32(kv.w);
            *(uint4*)&sQK[r * SKP + 4 * c4] = uk;
            float4 vv = *(const float4*)&Vg[(size_t)r * HD + 4 * c4];
            uint4 uv;
            uv.x = f2tf32(vv.x); uv.y = f2tf32(vv.y);
            uv.z = f2tf32(vv.z); uv.w = f2tf32(vv.w);
            *(uint4*)&sV[r * SVP + 4 * c4] = uv;
        }
        __syncthreads();

        // ---- S = Q @ K^T ----
        float sacc[8][4] = {};
        #pragma unroll
        for (int k = 0; k < 8; ++k) {
            #pragma unroll
            for (int nc = 0; nc < 8; ++nc) {
                uint32_t b0 = sQK[(8 * nc + gid) * SKP + 8 * k + tig];
                uint32_t b1 = sQK[(8 * nc + gid) * SKP + 8 * k + tig + 4];
                mma_tf32(sacc[nc], Aq[k][0], Aq[k][1], Aq[k][2], Aq[k][3], b0, b1);
            }
        }

        // ---- Online softmax (registers only) ----
        float mx0 = -1e30f, mx1 = -1e30f;
        #pragma unroll
        for (int nc = 0; nc < 8; ++nc) {
            mx0 = fmaxf(mx0, fmaxf(sacc[nc][0], sacc[nc][1]));
            mx1 = fmaxf(mx1, fmaxf(sacc[nc][2], sacc[nc][3]));
        }
        mx0 = fmaxf(mx0, __shfl_xor_sync(0xffffffffu, mx0, 1));
        mx0 = fmaxf(mx0, __shfl_xor_sync(0xffffffffu, mx0, 2));
        mx1 = fmaxf(mx1, __shfl_xor_sync(0xffffffffu, mx1, 1));
        mx1 = fmaxf(mx1, __shfl_xor_sync(0xffffffffu, mx1, 2));

        float mn0 = fmaxf(m0, mx0), mn1 = fmaxf(m1, mx1);
        float al0 = __expf(m0 - mn0), al1 = __expf(m1 - mn1);

        float sum0 = 0.f, sum1 = 0.f;
        #pragma unroll
        for (int nc = 0; nc < 8; ++nc) {
            sacc[nc][0] = __expf(sacc[nc][0] - mn0);
            sacc[nc][1] = __expf(sacc[nc][1] - mn0);
            sacc[nc][2] = __expf(sacc[nc][2] - mn1);
            sacc[nc][3] = __expf(sacc[nc][3] - mn1);
            sum0 += sacc[nc][0] + sacc[nc][1];
            sum1 += sacc[nc][2] + sacc[nc][3];
        }
        sum0 += __shfl_xor_sync(0xffffffffu, sum0, 1);
        sum0 += __shfl_xor_sync(0xffffffffu, sum0, 2);
        sum1 += __shfl_xor_sync(0xffffffffu, sum1, 1);
        sum1 += __shfl_xor_sync(0xffffffffu, sum1, 2);

        l0 = l0 * al0 + sum0;  m0 = mn0;
        l1 = l1 * al1 + sum1;  m1 = mn1;

        #pragma unroll
        for (int nc = 0; nc < 8; ++nc) {
            O[nc][0] *= al0; O[nc][1] *= al0;
            O[nc][2] *= al1; O[nc][3] *= al1;
        }

        // ---- Convert P to tf32 bits in place ----
        #pragma unroll
        for (int nc = 0; nc < 8; ++nc)
            #pragma unroll
            for (int j = 0; j < 4; ++j)
                sacc[nc][j] = __uint_as_float(f2tf32(sacc[nc][j]));

        // ---- O += P @ V ; A-fragments of P built via intra-quad shuffles ----
        #pragma unroll
        for (int ks = 0; ks < 8; ++ks) {
            float x0 = __shfl_sync(0xffffffffu, sacc[ks][0], src0);
            float x1 = __shfl_sync(0xffffffffu, sacc[ks][1], src0);
            float x2 = __shfl_sync(0xffffffffu, sacc[ks][2], src0);
            float x3 = __shfl_sync(0xffffffffu, sacc[ks][3], src0);
            float y0 = __shfl_sync(0xffffffffu, sacc[ks][0], src2);
            float y1 = __shfl_sync(0xffffffffu, sacc[ks][1], src2);
            float y2 = __shfl_sync(0xffffffffu, sacc[ks][2], src2);
            float y3 = __shfl_sync(0xffffffffu, sacc[ks][3], src2);
            uint32_t a0 = __float_as_uint(odd ? x1 : x0);  // row gid,   col 8ks+tig
            uint32_t a1 = __float_as_uint(odd ? x3 : x2);  // row gid+8, col 8ks+tig
            uint32_t a2 = __float_as_uint(odd ? y1 : y0);  // row gid,   col 8ks+tig+4
            uint32_t a3 = __float_as_uint(odd ? y3 : y2);  // row gid+8, col 8ks+tig+4
            #pragma unroll
            for (int nc = 0; nc < 8; ++nc) {
                uint32_t b0 = sV[(8 * ks + tig)     * SVP + 8 * nc + gid];
                uint32_t b1 = sV[(8 * ks + tig + 4) * SVP + 8 * nc + gid];
                mma_tf32(O[nc], a0, a1, a2, a3, b0, b1);
            }
        }
    }

    // ---- Write unnormalized partials + stats ----
    const size_t row0g = (size_t)b * SEQ + t0;
    float* Op = g_O4 + (size_t)split * BT * HD;
    #pragma unroll
    for (int nc = 0; nc < 8; ++nc) {
        int c = 8 * nc + 2 * tig;
        float* p0 = &Op[(row0g + mrow)     * HD + c];
        float* p1 = &Op[(row0g + mrow + 8) * HD + c];
        *(float2*)p0 = make_float2(O[nc][0], O[nc][1]);
        *(float2*)p1 = make_float2(O[nc][2], O[nc][3]);
    }
    if (tig == 0) {
        g_M4[split * BT + row0g + mrow]     = m0;
        g_M4[split * BT + row0g + mrow + 8] = m1;
        g_L4[split * BT + row0g + mrow]     = l0;
        g_L4[split * BT + row0g + mrow + 8] = l1;
    }
}

// ---------------------------------------------------------------------------
// Combine splits: O = sum_s w_s O_s / sum_s w_s l_s, w_s = exp(m_s - m*).
// One float4 per thread. grid = BT*HD/4/256 = 1024.
// ---------------------------------------------------------------------------
__global__ __launch_bounds__(256) void combine_kernel(float* __restrict__ out)
{
    int idx = blockIdx.x * 256 + threadIdx.x;      // float4 index
    int row = idx >> 4;                            // HD/4 = 16 float4 per row

    float m[NSPLIT], l[NSPLIT];
    float mstar = -1e30f;
    #pragma unroll
    for (int s = 0; s < NSPLIT; ++s) {
        m[s] = g_M4[s * BT + row];
        l[s] = g_L4[s * BT + row];
        mstar = fmaxf(mstar, m[s]);
    }
    float den = 0.f;
    float4 num = make_float4(0.f, 0.f, 0.f, 0.f);
    #pragma unroll
    for (int s = 0; s < NSPLIT; ++s) {
        float w = __expf(m[s] - mstar);
        den += w * l[s];
        float4 o = *(const float4*)&g_O4[(size_t)s * BT * HD + (size_t)idx * 4];
        num.x += w * o.x; num.y += w * o.y;
        num.z += w * o.z; num.w += w * o.w;
    }
    float inv = 1.0f / den;
    num.x *= inv; num.y *= inv; num.z *= inv; num.w *= inv;
    *(float4*)&out[(size_t)idx * 4] = num;
}

extern "C" void kernel_launch(void* const* d_in, const int* in_sizes, int n_in,
                              void* d_out, int out_size)
{
    const float* x  = (const float*)d_in[0];
    const float* wq = (const float*)d_in[1];
    const float* wk = (const float*)d_in[2];
    const float* wv = (const float*)d_in[3];
    float* out = (float*)d_out;

    proj_kernel<<<BT / 64, 128>>>(x, wq, wk, wv);

    dim3 gridA(SEQ / BM, BATCH, NSPLIT);
    attn_kernel<<<gridA, 128>>>();

    combine_kernel<<<BT * HD / 4 / 256, 256>>>(out);
}